// round 5
// baseline (speedup 1.0000x reference)
#include <cuda_runtime.h>

#define B_ 128
#define H_ 40
#define W_ 40
#define C_ 16
#define NPIX_ (B_*H_*W_)   /* 204800 */

/* Scratch (no allocations allowed): ping-pong state + pre-mask buffer. */
__device__ float g_state_buf[2][(size_t)NPIX_*C_];
__device__ float g_pre_buf[(size_t)NPIX_*C_];

typedef unsigned long long u64;

static __device__ __forceinline__ u64 pk2(float x){u64 r;asm("mov.b64 %0,{%1,%1};":"=l"(r):"f"(x));return r;}
static __device__ __forceinline__ u64 pkab(float a,float b){u64 r;asm("mov.b64 %0,{%1,%2};":"=l"(r):"f"(a),"f"(b));return r;}
static __device__ __forceinline__ void upk(u64 v,float&a,float&b){float x,y;asm("mov.b64 {%0,%1},%2;":"=f"(x),"=f"(y):"l"(v));a=x;b=y;}
static __device__ __forceinline__ u64 ffma2(u64 a,u64 b,u64 c){u64 d;asm("fma.rn.f32x2 %0,%1,%2,%3;":"=l"(d):"l"(a),"l"(b),"l"(c));return d;}
static __device__ __forceinline__ u64 fadd2(u64 a,u64 b){u64 d;asm("add.rn.f32x2 %0,%1,%2;":"=l"(d):"l"(a),"l"(b));return d;}

/* stacked frame + rgb writer for one pixel */
static __device__ __forceinline__ void write_frame(int f,int pix,const float4* v,
    float* stkF,float* rgbF,unsigned char* rgbU){
  size_t base=(size_t)f*NPIX_+pix;
  if(stkF){ float4* d=(float4*)(stkF+base*C_); d[0]=v[0];d[1]=v[1];d[2]=v[2];d[3]=v[3]; }
  if(rgbU||rgbF){
    float a=fminf(fmaxf(v[0].w,0.f),1.f);
    unsigned char r=(unsigned char)(fminf(fmaxf(1.f-a+v[0].x,0.f),1.f)*255.f);
    unsigned char g=(unsigned char)(fminf(fmaxf(1.f-a+v[0].y,0.f),1.f)*255.f);
    unsigned char b=(unsigned char)(fminf(fmaxf(1.f-a+v[0].z,0.f),1.f)*255.f);
    if(rgbU){ rgbU[base*3+0]=r; rgbU[base*3+1]=g; rgbU[base*3+2]=b; }
    if(rgbF){ rgbF[base*3+0]=(float)r; rgbF[base*3+1]=(float)g; rgbF[base*3+2]=(float)b; }
  }
}

/* ---- init: state[0] = input; emit frame 0 ---- */
__global__ void k_init(const float* __restrict__ st0,
                       float* stkF,float* rgbF,unsigned char* rgbU){
  int pix=blockIdx.x*blockDim.x+threadIdx.x;
  if(pix>=NPIX_) return;
  float4 v[4];
  const float4* s=(const float4*)(st0+(size_t)pix*C_);
  v[0]=s[0];v[1]=s[1];v[2]=s[2];v[3]=s[3];
  float4* d=(float4*)(g_state_buf[0]+(size_t)pix*C_);
  d[0]=v[0];d[1]=v[1];d[2]=v[2];d[3]=v[3];
  write_frame(0,pix,v,stkF,rgbF,rgbU);
}

/* ---- K1: pre = state + mask*MLP(perception(alive-masked state)) ----
 * grid (5,5,128) of 8x8 tiles; 256 thr = 16 pixel-quads x 16 hidden-groups.
 * Each thread: 4 pixels x 8 hidden (GEMM1); 4 px x 16 outs partial (GEMM2). */
__global__ void __launch_bounds__(256) k_pre(int sel,
    const float* __restrict__ W1,const float* __restrict__ b1,
    const float* __restrict__ W2,const int* __restrict__ umask)
{
  /* weight layouts: [..][16 jg][4 floats] -> 16-lane loads span 256B, conflict-free */
  __shared__ __align__(16) float sW1[48*2*16*4];   /* 24576 B : [i][ci][jg][4] */
  __shared__ __align__(16) float sW2[8*4*16*4];    /*  8192 B : [h][ci2][jg][4] */
  __shared__ float sb1[128];
  __shared__ __align__(16) float sP[48*64];        /* 12288 B ; first 144 reused as alpha halo */
  __shared__ float sM[8*110];                      /*  3520 B ; 8 ch x 10y x pitch11 */
  __shared__ float sAm[100];

  const int tid=threadIdx.x;
  const int b=blockIdx.z, by0=blockIdx.y*8, bx0=blockIdx.x*8;
  const float* __restrict__ sb=g_state_buf[sel]+(size_t)b*H_*W_*C_;

  /* stage W1: global [j(128)][i(48)] -> sW1[i][(j>>2)&1][j>>3][j&3] */
  for(int idx=tid; idx<6144; idx+=256){
    int j=idx/48, i=idx-j*48;
    sW1[((((i<<1)+((j>>2)&1))<<4) + (j>>3))*4 + (j&3)] = W1[idx];
  }
  /* stage W2: global [o(16)][j(128)] -> sW2[j&7][o>>2][j>>3][o&3] */
  for(int idx=tid; idx<2048; idx+=256){
    int o=idx>>7, j=idx&127;
    sW2[((((j&7)<<2)+(o>>2))*16 + (j>>3))*4 + (o&3)] = W2[idx];
  }
  if(tid<128) sb1[tid]=b1[tid];
  /* alpha with halo 2 into sP[0..143] (OOB=-inf) */
  for(int idx=tid; idx<144; idx+=256){
    int ay=idx/12, ax=idx-ay*12;
    int gy=by0-2+ay, gx=bx0-2+ax;
    float a=-1e30f;
    if((unsigned)gy<(unsigned)H_ && (unsigned)gx<(unsigned)W_) a=sb[(gy*W_+gx)*C_+3];
    sP[idx]=a;
  }
  __syncthreads();

  /* alive mask on 10x10 (halo 1) */
  for(int idx=tid; idx<100; idx+=256){
    int my=idx/10, mx=idx-my*10;
    const float* a0=&sP[my*12+mx];
    float m=a0[0]; m=fmaxf(m,a0[1]); m=fmaxf(m,a0[2]);
    m=fmaxf(m,a0[12]); m=fmaxf(m,a0[13]); m=fmaxf(m,a0[14]);
    m=fmaxf(m,a0[24]); m=fmaxf(m,a0[25]); m=fmaxf(m,a0[26]);
    sAm[idx]=(m>=0.1f)?1.0f:0.0f;
  }
  __syncthreads();

  /* build perception sP[48][64] in two 8-channel halves through sM */
  for(int h=0;h<2;h++){
    for(int idx=tid; idx<200; idx+=256){
      int p2=idx>>1, c4h=idx&1;
      int my=p2/10, mx=p2-my*10;
      int gy=by0-1+my, gx=bx0-1+mx;
      float4 v=make_float4(0.f,0.f,0.f,0.f);
      if((unsigned)gy<(unsigned)H_ && (unsigned)gx<(unsigned)W_)
        v=*(const float4*)&sb[(gy*W_+gx)*C_ + h*8 + c4h*4];
      float am=sAm[p2];
      int cc0=c4h*4, rb=my*11+mx;
      sM[(cc0  )*110+rb]=v.x*am;
      sM[(cc0+1)*110+rb]=v.y*am;
      sM[(cc0+2)*110+rb]=v.z*am;
      sM[(cc0+3)*110+rb]=v.w*am;
    }
    __syncthreads();
    for(int idx=tid; idx<512; idx+=256){
      int cc=idx>>6, p=idx&63;
      int py=p>>3, px=p&7;
      const float* m=&sM[cc*110 + py*11 + px];
      float m00=m[0],  m01=m[1],  m02=m[2];
      float m10=m[11], m11=m[12], m12=m[13];
      float m20=m[22], m21=m[23], m22=m[24];
      int cg=h*8+cc;
      sP[cg*64+p]      = m11;
      sP[(16+cg)*64+p] = ((m02+2.f*m12+m22)-(m00+2.f*m10+m20))*0.125f;
      sP[(32+cg)*64+p] = ((m20+2.f*m21+m22)-(m00+2.f*m01+m02))*0.125f;
    }
    __syncthreads();
  }

  const int jg=tid&15, pp=tid>>4;   /* pixel base p = pp*4 ; hidden base = jg*8 */

  /* acc[hp][px]: hidden pair (jg*8+2hp, +1) packed f32x2, init = bias */
  u64 acc[4][4];
#pragma unroll
  for(int hp=0;hp<4;hp++){
    u64 bb=pkab(sb1[jg*8+2*hp], sb1[jg*8+2*hp+1]);
#pragma unroll
    for(int p=0;p<4;p++) acc[hp][p]=bb;
  }

  const ulonglong2* sW1v=(const ulonglong2*)sW1;
  const ulonglong2* sW2v=(const ulonglong2*)sW2;

  /* GEMM1: 48 perception comps -> 8 hidden for 4 px */
#pragma unroll 4
  for(int i=0;i<48;i++){
    float4 pv=*(const float4*)&sP[i*64 + pp*4];
    u64 pd0=pk2(pv.x), pd1=pk2(pv.y), pd2=pk2(pv.z), pd3=pk2(pv.w);
    ulonglong2 wA=sW1v[(i*2+0)*16 + jg];
    ulonglong2 wB=sW1v[(i*2+1)*16 + jg];
    acc[0][0]=ffma2(wA.x,pd0,acc[0][0]); acc[0][1]=ffma2(wA.x,pd1,acc[0][1]);
    acc[0][2]=ffma2(wA.x,pd2,acc[0][2]); acc[0][3]=ffma2(wA.x,pd3,acc[0][3]);
    acc[1][0]=ffma2(wA.y,pd0,acc[1][0]); acc[1][1]=ffma2(wA.y,pd1,acc[1][1]);
    acc[1][2]=ffma2(wA.y,pd2,acc[1][2]); acc[1][3]=ffma2(wA.y,pd3,acc[1][3]);
    acc[2][0]=ffma2(wB.x,pd0,acc[2][0]); acc[2][1]=ffma2(wB.x,pd1,acc[2][1]);
    acc[2][2]=ffma2(wB.x,pd2,acc[2][2]); acc[2][3]=ffma2(wB.x,pd3,acc[2][3]);
    acc[3][0]=ffma2(wB.y,pd0,acc[3][0]); acc[3][1]=ffma2(wB.y,pd1,acc[3][1]);
    acc[3][2]=ffma2(wB.y,pd2,acc[3][2]); acc[3][3]=ffma2(wB.y,pd3,acc[3][3]);
  }

  /* ReLU + GEMM2: 8 hidden -> 16 outputs (pairs packed) for 4 px */
  u64 u[8][4];
#pragma unroll
  for(int k=0;k<8;k++){u[k][0]=0ull;u[k][1]=0ull;u[k][2]=0ull;u[k][3]=0ull;}
#pragma unroll
  for(int hp=0;hp<4;hp++){
    u64 hv0[4],hv1[4];
#pragma unroll
    for(int p=0;p<4;p++){
      float a,bv; upk(acc[hp][p],a,bv);
      hv0[p]=pk2(fmaxf(a,0.f));
      hv1[p]=pk2(fmaxf(bv,0.f));
    }
#pragma unroll
    for(int ci=0;ci<4;ci++){
      ulonglong2 w=sW2v[(((2*hp  )<<2)+ci)*16 + jg];
      u[2*ci  ][0]=ffma2(w.x,hv0[0],u[2*ci  ][0]);
      u[2*ci  ][1]=ffma2(w.x,hv0[1],u[2*ci  ][1]);
      u[2*ci  ][2]=ffma2(w.x,hv0[2],u[2*ci  ][2]);
      u[2*ci  ][3]=ffma2(w.x,hv0[3],u[2*ci  ][3]);
      u[2*ci+1][0]=ffma2(w.y,hv0[0],u[2*ci+1][0]);
      u[2*ci+1][1]=ffma2(w.y,hv0[1],u[2*ci+1][1]);
      u[2*ci+1][2]=ffma2(w.y,hv0[2],u[2*ci+1][2]);
      u[2*ci+1][3]=ffma2(w.y,hv0[3],u[2*ci+1][3]);
    }
#pragma unroll
    for(int ci=0;ci<4;ci++){
      ulonglong2 w=sW2v[(((2*hp+1)<<2)+ci)*16 + jg];
      u[2*ci  ][0]=ffma2(w.x,hv1[0],u[2*ci  ][0]);
      u[2*ci  ][1]=ffma2(w.x,hv1[1],u[2*ci  ][1]);
      u[2*ci  ][2]=ffma2(w.x,hv1[2],u[2*ci  ][2]);
      u[2*ci  ][3]=ffma2(w.x,hv1[3],u[2*ci  ][3]);
      u[2*ci+1][0]=ffma2(w.y,hv1[0],u[2*ci+1][0]);
      u[2*ci+1][1]=ffma2(w.y,hv1[1],u[2*ci+1][1]);
      u[2*ci+1][2]=ffma2(w.y,hv1[2],u[2*ci+1][2]);
      u[2*ci+1][3]=ffma2(w.y,hv1[3],u[2*ci+1][3]);
    }
  }

  /* reduce over 16 hidden-groups (lane bits 0..3) */
#pragma unroll
  for(int k=0;k<8;k++){
#pragma unroll
    for(int p=0;p<4;p++){
      u[k][p]=fadd2(u[k][p], __shfl_xor_sync(0xffffffffu,u[k][p],1));
      u[k][p]=fadd2(u[k][p], __shfl_xor_sync(0xffffffffu,u[k][p],2));
      u[k][p]=fadd2(u[k][p], __shfl_xor_sync(0xffffffffu,u[k][p],4));
      u[k][p]=fadd2(u[k][p], __shfl_xor_sync(0xffffffffu,u[k][p],8));
    }
  }

  if(jg==0){
    int py=pp>>1, px0=(pp&1)*4;
    int gy=by0+py, gx0=bx0+px0;
    int4 m4=*(const int4*)&umask[(b*H_+gy)*W_+gx0];
    int mv[4]; mv[0]=m4.x; mv[1]=m4.y; mv[2]=m4.z; mv[3]=m4.w;
#pragma unroll
    for(int p=0;p<4;p++){
      float o_[16];
#pragma unroll
      for(int op=0;op<8;op++) upk(u[op][p], o_[2*op], o_[2*op+1]);
      float mf=(float)mv[p];
      const float4* s=(const float4*)&sb[(gy*W_+gx0+p)*C_];
      float4* d=(float4*)(g_pre_buf+((size_t)(b*H_+gy)*W_+gx0+p)*C_);
#pragma unroll
      for(int c4=0;c4<4;c4++){
        float4 a=s[c4];
        a.x+=mf*o_[4*c4+0]; a.y+=mf*o_[4*c4+1];
        a.z+=mf*o_[4*c4+2]; a.w+=mf*o_[4*c4+3];
        d[c4]=a;
      }
    }
  }
}

/* ---- K2: new = pre * alive_mask(pre); store state + frame ---- */
__global__ void k_post(int nsel,int f,float* stkF,float* rgbF,unsigned char* rgbU){
  int pix=blockIdx.x*blockDim.x+threadIdx.x;
  if(pix>=NPIX_) return;
  int b=pix/(H_*W_); int rem=pix-b*(H_*W_); int y=rem/W_; int x=rem-y*W_;
  float m=-1e30f;
#pragma unroll
  for(int dy=-1;dy<=1;dy++){
    int yy=y+dy; if((unsigned)yy>=(unsigned)H_) continue;
#pragma unroll
    for(int dx=-1;dx<=1;dx++){
      int xx=x+dx; if((unsigned)xx>=(unsigned)W_) continue;
      m=fmaxf(m, g_pre_buf[((size_t)(b*H_+yy)*W_+xx)*C_+3]);
    }
  }
  float am=(m>=0.1f)?1.0f:0.0f;
  const float4* s=(const float4*)(g_pre_buf+(size_t)pix*C_);
  float4 v[4];
#pragma unroll
  for(int c4=0;c4<4;c4++){
    float4 t=s[c4];
    t.x*=am; t.y*=am; t.z*=am; t.w*=am;
    v[c4]=t;
  }
  float4* d=(float4*)(g_state_buf[nsel]+(size_t)pix*C_);
  d[0]=v[0];d[1]=v[1];d[2]=v[2];d[3]=v[3];
  write_frame(f,pix,v,stkF,rgbF,rgbU);
}

extern "C" void kernel_launch(void* const* d_in, const int* in_sizes, int n_in,
                              void* d_out, int out_size) {
  const float* st0=(const float*)d_in[0];
  const float* W1 =(const float*)d_in[1];
  const float* b1 =(const float*)d_in[2];
  const float* W2 =(const float*)d_in[3];
  const int*   um =(const int*)d_in[4];

  const long long SZ_RGB=33LL*NPIX_*3;     /* 20,275,200  */
  const long long SZ_STK=33LL*NPIX_*16;    /* 108,134,400 */

  float* stkF=0; float* rgbF=0; unsigned char* rgbU=0;
  long long osz=(long long)out_size;
  if(osz==SZ_RGB+SZ_STK){               /* float concat: rgb-as-float, then stacked */
    rgbF=(float*)d_out; stkF=(float*)d_out+SZ_RGB;
  }else if(osz==SZ_STK){                /* stacked only */
    stkF=(float*)d_out;
  }else if(osz==SZ_RGB){                /* rgb u8 only */
    rgbU=(unsigned char*)d_out;
  }else{                                /* byte concat: rgb u8, then stacked bytes */
    rgbU=(unsigned char*)d_out;
    stkF=(float*)((char*)d_out+SZ_RGB);
  }

  const int TB=256, NB=(NPIX_+TB-1)/TB;
  k_init<<<NB,TB>>>(st0,stkF,rgbF,rgbU);
  int sel=0;
  for(int t=0;t<32;t++){
    k_pre<<<dim3(5,5,B_),256>>>(sel,W1,b1,W2,um+(size_t)t*NPIX_);
    k_post<<<NB,TB>>>(sel^1,t+1,stkF,rgbF,rgbU);
    sel^=1;
  }
}

// round 9
// speedup vs baseline: 1.0600x; 1.0600x over previous
#include <cuda_runtime.h>

#define B_ 128
#define H_ 40
#define W_ 40
#define C_ 16
#define NPIX_ (B_*H_*W_)   /* 204800 */

/* Scratch (no allocations allowed): ping-pong state + pre-mask buffer. */
__device__ float g_state_buf[2][(size_t)NPIX_*C_];
__device__ float g_pre_buf[(size_t)NPIX_*C_];

typedef unsigned long long u64;

static __device__ __forceinline__ u64 pk2(float x){u64 r;asm("mov.b64 %0,{%1,%1};":"=l"(r):"f"(x));return r;}
static __device__ __forceinline__ void upk(u64 v,float&a,float&b){float x,y;asm("mov.b64 {%0,%1},%2;":"=f"(x),"=f"(y):"l"(v));a=x;b=y;}
static __device__ __forceinline__ u64 ffma2(u64 a,u64 b,u64 c){u64 d;asm("fma.rn.f32x2 %0,%1,%2,%3;":"=l"(d):"l"(a),"l"(b),"l"(c));return d;}
static __device__ __forceinline__ u64 fadd2(u64 a,u64 b){u64 d;asm("add.rn.f32x2 %0,%1,%2;":"=l"(d):"l"(a),"l"(b));return d;}

/* stacked frame + rgb writer for one pixel */
static __device__ __forceinline__ void write_frame(int f,int pix,const float4* v,
    float* stkF,float* rgbF,unsigned char* rgbU){
  size_t base=(size_t)f*NPIX_+pix;
  if(stkF){ float4* d=(float4*)(stkF+base*C_); d[0]=v[0];d[1]=v[1];d[2]=v[2];d[3]=v[3]; }
  if(rgbU||rgbF){
    float a=fminf(fmaxf(v[0].w,0.f),1.f);
    unsigned char r=(unsigned char)(fminf(fmaxf(1.f-a+v[0].x,0.f),1.f)*255.f);
    unsigned char g=(unsigned char)(fminf(fmaxf(1.f-a+v[0].y,0.f),1.f)*255.f);
    unsigned char b=(unsigned char)(fminf(fmaxf(1.f-a+v[0].z,0.f),1.f)*255.f);
    if(rgbU){ rgbU[base*3+0]=r; rgbU[base*3+1]=g; rgbU[base*3+2]=b; }
    if(rgbF){ rgbF[base*3+0]=(float)r; rgbF[base*3+1]=(float)g; rgbF[base*3+2]=(float)b; }
  }
}

/* ---- init: state[0] = input; emit frame 0 ---- */
__global__ void k_init(const float* __restrict__ st0,
                       float* stkF,float* rgbF,unsigned char* rgbU){
  int pix=blockIdx.x*blockDim.x+threadIdx.x;
  if(pix>=NPIX_) return;
  float4 v[4];
  const float4* s=(const float4*)(st0+(size_t)pix*C_);
  v[0]=s[0];v[1]=s[1];v[2]=s[2];v[3]=s[3];
  float4* d=(float4*)(g_state_buf[0]+(size_t)pix*C_);
  d[0]=v[0];d[1]=v[1];d[2]=v[2];d[3]=v[3];
  write_frame(0,pix,v,stkF,rgbF,rgbU);
}

/* smem layout offsets (floats) inside one 48KB flat buffer */
#define OFF_W1 0        /* 6144 floats : u64[(i*4+hp)*16+jg]              */
#define OFF_W2 6144     /* 2048 floats : u64[(lh*8+op)*16+jg]             */
#define OFF_P  8192     /* 3072 floats : sP[i][64]                        */
#define OFF_M  11264    /* 880  floats : sM[8ch][110] pitch 11            */
#define OFF_AL 12144    /* 144  floats : alpha halo 12x12                 */
/* total 12288 floats = 49152 B */

/* ---- K1: pre = state + mask*MLP(perception(alive-masked state)) ----
 * grid (5,5,128) of 8x8 tiles; 128 thr = 8 px-rows x 16 hidden-groups.
 * Each thread: 8 pixels (one tile row) x 8 hidden (GEMM1); GEMM2 in two
 * 4-px halves from registers with shfl reduction over the 16 jg lanes.  */
__global__ void __launch_bounds__(128) k_pre(int sel,
    const float* __restrict__ W1,const float* __restrict__ b1,
    const float* __restrict__ W2,const int* __restrict__ umask)
{
  __shared__ __align__(16) float sm[12288];

  const int tid=threadIdx.x;
  const int b=blockIdx.z, by0=blockIdx.y*8, bx0=blockIdx.x*8;
  const float* __restrict__ sb=g_state_buf[sel]+(size_t)b*H_*W_*C_;

  /* stage W1: global [j(128)][i(48)] -> u64 pairs [(i*4+hp)*16+jg][lo|hi] */
  for(int idx=tid; idx<6144; idx+=128){
    int j=idx/48, i=idx-j*48;
    int jg=j>>3, lh=j&7;
    sm[OFF_W1 + (((i*4+(lh>>1))*16 + jg)<<1) + (lh&1)] = W1[idx];
  }
  /* stage W2: global [o(16)][j(128)] -> u64 pairs [(lh*8+op)*16+jg][o&1] */
  for(int idx=tid; idx<2048; idx+=128){
    int o=idx>>7, j=idx&127;
    int jg=j>>3, lh=j&7;
    sm[OFF_W2 + (((lh*8+(o>>1))*16 + jg)<<1) + (o&1)] = W2[idx];
  }
  /* alpha with halo 2 (OOB=-inf) */
  for(int idx=tid; idx<144; idx+=128){
    int ay=idx/12, ax=idx-ay*12;
    int gy=by0-2+ay, gx=bx0-2+ax;
    float a=-1e30f;
    if((unsigned)gy<(unsigned)H_ && (unsigned)gx<(unsigned)W_) a=sb[(gy*W_+gx)*C_+3];
    sm[OFF_AL+idx]=a;
  }
  __syncthreads();

  /* build perception sP[48][64] in two 8-channel halves through sM */
  for(int h=0;h<2;h++){
    for(int idx=tid; idx<200; idx+=128){
      int p2=idx>>1, c4h=idx&1;
      int my=p2/10, mx=p2-my*10;
      /* alive mask for this (my,mx) from alpha halo */
      const float* a0=&sm[OFF_AL + my*12+mx];
      float mm=a0[0]; mm=fmaxf(mm,a0[1]); mm=fmaxf(mm,a0[2]);
      mm=fmaxf(mm,a0[12]); mm=fmaxf(mm,a0[13]); mm=fmaxf(mm,a0[14]);
      mm=fmaxf(mm,a0[24]); mm=fmaxf(mm,a0[25]); mm=fmaxf(mm,a0[26]);
      float am=(mm>=0.1f)?1.0f:0.0f;
      int gy=by0-1+my, gx=bx0-1+mx;
      float4 v=make_float4(0.f,0.f,0.f,0.f);
      if((unsigned)gy<(unsigned)H_ && (unsigned)gx<(unsigned)W_)
        v=*(const float4*)&sb[(gy*W_+gx)*C_ + h*8 + c4h*4];
      int cc0=c4h*4, rb=my*11+mx;
      sm[OFF_M+(cc0  )*110+rb]=v.x*am;
      sm[OFF_M+(cc0+1)*110+rb]=v.y*am;
      sm[OFF_M+(cc0+2)*110+rb]=v.z*am;
      sm[OFF_M+(cc0+3)*110+rb]=v.w*am;
    }
    __syncthreads();
    for(int idx=tid; idx<512; idx+=128){
      int cc=idx>>6, p=idx&63;
      int py=p>>3, px=p&7;
      const float* m=&sm[OFF_M + cc*110 + py*11 + px];
      float m00=m[0],  m01=m[1],  m02=m[2];
      float m10=m[11], m11=m[12], m12=m[13];
      float m20=m[22], m21=m[23], m22=m[24];
      int cg=h*8+cc;
      sm[OFF_P+cg*64+p]      = m11;
      sm[OFF_P+(16+cg)*64+p] = ((m02+2.f*m12+m22)-(m00+2.f*m10+m20))*0.125f;
      sm[OFF_P+(32+cg)*64+p] = ((m20+2.f*m21+m22)-(m00+2.f*m01+m02))*0.125f;
    }
    __syncthreads();
  }

  const int jg=tid&15, pg=tid>>4;    /* thread: tile row pg, hidden jg*8..+7 */
  const u64* sW1u=(const u64*)&sm[OFF_W1];
  const u64* sW2u=(const u64*)&sm[OFF_W2];

  /* acc[hp][px]: hidden pair (jg*8+2hp, +1) packed f32x2, init = bias (global) */
  u64 acc[4][8];
  {
    const u64* bp=(const u64*)b1;   /* aligned 8B pairs */
#pragma unroll
    for(int hp=0;hp<4;hp++){
      u64 bb=__ldg(&bp[jg*4+hp]);
#pragma unroll
      for(int p=0;p<8;p++) acc[hp][p]=bb;
    }
  }

  /* GEMM1: 48 comps -> 8 hidden x 8 px. weights: LDS.64 conflict-free */
#pragma unroll 2
  for(int i=0;i<48;i++){
    u64 w0=sW1u[(i*4+0)*16+jg];
    u64 w1=sW1u[(i*4+1)*16+jg];
    u64 w2=sW1u[(i*4+2)*16+jg];
    u64 w3=sW1u[(i*4+3)*16+jg];
    float4 pva=*(const float4*)&sm[OFF_P + i*64 + pg*8];
    float4 pvb=*(const float4*)&sm[OFF_P + i*64 + pg*8 + 4];
    u64 pd[8];
    pd[0]=pk2(pva.x); pd[1]=pk2(pva.y); pd[2]=pk2(pva.z); pd[3]=pk2(pva.w);
    pd[4]=pk2(pvb.x); pd[5]=pk2(pvb.y); pd[6]=pk2(pvb.z); pd[7]=pk2(pvb.w);
#pragma unroll
    for(int p=0;p<8;p++){
      acc[0][p]=ffma2(w0,pd[p],acc[0][p]);
      acc[1][p]=ffma2(w1,pd[p],acc[1][p]);
      acc[2][p]=ffma2(w2,pd[p],acc[2][p]);
      acc[3][p]=ffma2(w3,pd[p],acc[3][p]);
    }
  }

  /* GEMM2 + reduce + store, in two 4-pixel halves (register-lean) */
  const int gy=by0+pg;
#pragma unroll
  for(int half=0;half<2;half++){
    const int po=half*4;
    u64 u[8][4];
#pragma unroll
    for(int k=0;k<8;k++){u[k][0]=0ull;u[k][1]=0ull;u[k][2]=0ull;u[k][3]=0ull;}
#pragma unroll
    for(int hp=0;hp<4;hp++){
      u64 hvL[4],hvH[4];
#pragma unroll
      for(int p=0;p<4;p++){
        float a,bv; upk(acc[hp][po+p],a,bv);
        hvL[p]=pk2(fmaxf(a,0.f));
        hvH[p]=pk2(fmaxf(bv,0.f));
      }
#pragma unroll
      for(int op=0;op<8;op++){
        u64 w=sW2u[((2*hp  )*8+op)*16+jg];
        u[op][0]=ffma2(w,hvL[0],u[op][0]);
        u[op][1]=ffma2(w,hvL[1],u[op][1]);
        u[op][2]=ffma2(w,hvL[2],u[op][2]);
        u[op][3]=ffma2(w,hvL[3],u[op][3]);
      }
#pragma unroll
      for(int op=0;op<8;op++){
        u64 w=sW2u[((2*hp+1)*8+op)*16+jg];
        u[op][0]=ffma2(w,hvH[0],u[op][0]);
        u[op][1]=ffma2(w,hvH[1],u[op][1]);
        u[op][2]=ffma2(w,hvH[2],u[op][2]);
        u[op][3]=ffma2(w,hvH[3],u[op][3]);
      }
    }
    /* reduce over 16 jg lanes (lane bits 0..3) */
#pragma unroll
    for(int k=0;k<8;k++){
#pragma unroll
      for(int p=0;p<4;p++){
        u[k][p]=fadd2(u[k][p], __shfl_xor_sync(0xffffffffu,u[k][p],1));
        u[k][p]=fadd2(u[k][p], __shfl_xor_sync(0xffffffffu,u[k][p],2));
        u[k][p]=fadd2(u[k][p], __shfl_xor_sync(0xffffffffu,u[k][p],4));
        u[k][p]=fadd2(u[k][p], __shfl_xor_sync(0xffffffffu,u[k][p],8));
      }
    }
    if(jg==0){
      int gx0=bx0+po;
      int4 m4=*(const int4*)&umask[(b*H_+gy)*W_+gx0];
      int mv[4]; mv[0]=m4.x; mv[1]=m4.y; mv[2]=m4.z; mv[3]=m4.w;
#pragma unroll
      for(int p=0;p<4;p++){
        float o_[16];
#pragma unroll
        for(int op=0;op<8;op++) upk(u[op][p], o_[2*op], o_[2*op+1]);
        float mf=(float)mv[p];
        const float4* s=(const float4*)&sb[(gy*W_+gx0+p)*C_];
        float4* d=(float4*)(g_pre_buf+((size_t)(b*H_+gy)*W_+gx0+p)*C_);
#pragma unroll
        for(int c4=0;c4<4;c4++){
          float4 a=s[c4];
          a.x+=mf*o_[4*c4+0]; a.y+=mf*o_[4*c4+1];
          a.z+=mf*o_[4*c4+2]; a.w+=mf*o_[4*c4+3];
          d[c4]=a;
        }
      }
    }
  }
}

/* ---- K2: new = pre * alive_mask(pre); store state + frame ---- */
__global__ void k_post(int nsel,int f,float* stkF,float* rgbF,unsigned char* rgbU){
  int pix=blockIdx.x*blockDim.x+threadIdx.x;
  if(pix>=NPIX_) return;
  int b=pix/(H_*W_); int rem=pix-b*(H_*W_); int y=rem/W_; int x=rem-y*W_;
  float m=-1e30f;
#pragma unroll
  for(int dy=-1;dy<=1;dy++){
    int yy=y+dy; if((unsigned)yy>=(unsigned)H_) continue;
#pragma unroll
    for(int dx=-1;dx<=1;dx++){
      int xx=x+dx; if((unsigned)xx>=(unsigned)W_) continue;
      m=fmaxf(m, g_pre_buf[((size_t)(b*H_+yy)*W_+xx)*C_+3]);
    }
  }
  float am=(m>=0.1f)?1.0f:0.0f;
  const float4* s=(const float4*)(g_pre_buf+(size_t)pix*C_);
  float4 v[4];
#pragma unroll
  for(int c4=0;c4<4;c4++){
    float4 t=s[c4];
    t.x*=am; t.y*=am; t.z*=am; t.w*=am;
    v[c4]=t;
  }
  float4* d=(float4*)(g_state_buf[nsel]+(size_t)pix*C_);
  d[0]=v[0];d[1]=v[1];d[2]=v[2];d[3]=v[3];
  write_frame(f,pix,v,stkF,rgbF,rgbU);
}

extern "C" void kernel_launch(void* const* d_in, const int* in_sizes, int n_in,
                              void* d_out, int out_size) {
  const float* st0=(const float*)d_in[0];
  const float* W1 =(const float*)d_in[1];
  const float* b1 =(const float*)d_in[2];
  const float* W2 =(const float*)d_in[3];
  const int*   um =(const int*)d_in[4];

  const long long SZ_RGB=33LL*NPIX_*3;     /* 20,275,200  */
  const long long SZ_STK=33LL*NPIX_*16;    /* 108,134,400 */

  float* stkF=0; float* rgbF=0; unsigned char* rgbU=0;
  long long osz=(long long)out_size;
  if(osz==SZ_RGB+SZ_STK){               /* float concat: rgb-as-float, then stacked */
    rgbF=(float*)d_out; stkF=(float*)d_out+SZ_RGB;
  }else if(osz==SZ_STK){                /* stacked only */
    stkF=(float*)d_out;
  }else if(osz==SZ_RGB){                /* rgb u8 only */
    rgbU=(unsigned char*)d_out;
  }else{                                /* byte concat: rgb u8, then stacked bytes */
    rgbU=(unsigned char*)d_out;
    stkF=(float*)((char*)d_out+SZ_RGB);
  }

  const int TB=256, NB=(NPIX_+TB-1)/TB;
  k_init<<<NB,TB>>>(st0,stkF,rgbF,rgbU);
  int sel=0;
  for(int t=0;t<32;t++){
    k_pre<<<dim3(5,5,B_),128>>>(sel,W1,b1,W2,um+(size_t)t*NPIX_);
    k_post<<<NB,TB>>>(sel^1,t+1,stkF,rgbF,rgbU);
    sel^=1;
  }
}

// round 13
// speedup vs baseline: 1.2430x; 1.1726x over previous
#include <cuda_runtime.h>

#define B_ 128
#define H_ 40
#define W_ 40
#define C_ 16
#define NPIX_ (B_*H_*W_)   /* 204800 */

/* Scratch (no allocations allowed): ping-pong state + pre-mask buffer. */
__device__ float g_state_buf[2][(size_t)NPIX_*C_];
__device__ float g_pre_buf[(size_t)NPIX_*C_];

typedef unsigned long long u64;

static __device__ __forceinline__ u64 pk2(float x){u64 r;asm("mov.b64 %0,{%1,%1};":"=l"(r):"f"(x));return r;}
static __device__ __forceinline__ u64 pkab(float a,float b){u64 r;asm("mov.b64 %0,{%1,%2};":"=l"(r):"f"(a),"f"(b));return r;}
static __device__ __forceinline__ void upk(u64 v,float&a,float&b){float x,y;asm("mov.b64 {%0,%1},%2;":"=f"(x),"=f"(y):"l"(v));a=x;b=y;}
static __device__ __forceinline__ u64 ffma2(u64 a,u64 b,u64 c){u64 d;asm("fma.rn.f32x2 %0,%1,%2,%3;":"=l"(d):"l"(a),"l"(b),"l"(c));return d;}
static __device__ __forceinline__ u64 fadd2(u64 a,u64 b){u64 d;asm("add.rn.f32x2 %0,%1,%2;":"=l"(d):"l"(a),"l"(b));return d;}

/* stacked frame + rgb writer for one pixel */
static __device__ __forceinline__ void write_frame(int f,int pix,const float4* v,
    float* stkF,float* rgbF,unsigned char* rgbU){
  size_t base=(size_t)f*NPIX_+pix;
  if(stkF){ float4* d=(float4*)(stkF+base*C_); d[0]=v[0];d[1]=v[1];d[2]=v[2];d[3]=v[3]; }
  if(rgbU||rgbF){
    float a=fminf(fmaxf(v[0].w,0.f),1.f);
    unsigned char r=(unsigned char)(fminf(fmaxf(1.f-a+v[0].x,0.f),1.f)*255.f);
    unsigned char g=(unsigned char)(fminf(fmaxf(1.f-a+v[0].y,0.f),1.f)*255.f);
    unsigned char b=(unsigned char)(fminf(fmaxf(1.f-a+v[0].z,0.f),1.f)*255.f);
    if(rgbU){ rgbU[base*3+0]=r; rgbU[base*3+1]=g; rgbU[base*3+2]=b; }
    if(rgbF){ rgbF[base*3+0]=(float)r; rgbF[base*3+1]=(float)g; rgbF[base*3+2]=(float)b; }
  }
}

/* ---- init: state[0] = input; emit frame 0 ---- */
__global__ void k_init(const float* __restrict__ st0,
                       float* stkF,float* rgbF,unsigned char* rgbU){
  int pix=blockIdx.x*blockDim.x+threadIdx.x;
  if(pix>=NPIX_) return;
  float4 v[4];
  const float4* s=(const float4*)(st0+(size_t)pix*C_);
  v[0]=s[0];v[1]=s[1];v[2]=s[2];v[3]=s[3];
  float4* d=(float4*)(g_state_buf[0]+(size_t)pix*C_);
  d[0]=v[0];d[1]=v[1];d[2]=v[2];d[3]=v[3];
  write_frame(0,pix,v,stkF,rgbF,rgbU);
}

/* dynamic smem layout (floats):
 *  OFF_W1    : 6144  u64-pairs laid out exactly like global W1 [j][48]
 *  OFF_W2    : 2048  transposed  [j][16]
 *  OFF_B1    : 128
 *  OFF_MASK  : 16ch x 252  (6 rows x 42 cols, tile rows y0-1..y0+4, cols -1..40)
 *  OFF_ALIVE : 252
 *  OFF_ALPHA : 352   (8 rows x 44 cols, rows y0-2..y0+5, cols -2..41)
 */
#define OFF_W1    0
#define OFF_W2    6144
#define OFF_B1    8192
#define OFF_MASK  8320
#define OFF_ALIVE 12352
#define OFF_ALPHA 12604
#define SMEM_FLOATS 12956
#define SMEM_BYTES  (SMEM_FLOATS*4)

/* ---- K1: pre = state + mask*MLP(perception(alive-masked state)) ----
 * grid (10, 128): one 40x4 row-strip per block; 160 threads = 1 px each.
 * All weight loads are warp-uniform smem broadcasts; no cross-lane reduce. */
__global__ void __launch_bounds__(160,4) k_pre(int sel,
    const float* __restrict__ W1,const float* __restrict__ b1,
    const float* __restrict__ W2,const int* __restrict__ umask)
{
  extern __shared__ __align__(16) float sm[];
  const int tid=threadIdx.x;
  const int b=blockIdx.y, y0=blockIdx.x*4;
  const float* __restrict__ sb=g_state_buf[sel]+(size_t)b*H_*W_*C_;

  /* stage W1 verbatim (layout already [j][i] row-major, i-pairs contiguous) */
  {
    const float4* src=(const float4*)W1;
    float4* dst=(float4*)&sm[OFF_W1];
    for(int idx=tid; idx<1536; idx+=160) dst[idx]=src[idx];
  }
  /* stage W2 transposed: [o][j] -> [j][16] */
  for(int idx=tid; idx<2048; idx+=160){
    int o=idx>>7, j=idx&127;
    sm[OFF_W2 + j*16 + o] = W2[idx];
  }
  for(int idx=tid; idx<128; idx+=160) sm[OFF_B1+idx]=b1[idx];
  /* alpha halo 8x44 (OOB=-inf) */
  for(int idx=tid; idx<352; idx+=160){
    int ay=idx/44, ax=idx-ay*44;
    int gy=y0-2+ay, gx=ax-2;
    float a=-1e30f;
    if((unsigned)gy<(unsigned)H_ && (unsigned)gx<(unsigned)W_) a=sb[(gy*W_+gx)*C_+3];
    sm[OFF_ALPHA+idx]=a;
  }
  __syncthreads();

  /* alive mask 6x42 */
  for(int idx=tid; idx<252; idx+=160){
    int ay=idx/42, ax=idx-ay*42;
    const float* a0=&sm[OFF_ALPHA + ay*44 + ax];
    float m=a0[0]; m=fmaxf(m,a0[1]); m=fmaxf(m,a0[2]);
    m=fmaxf(m,a0[44]); m=fmaxf(m,a0[45]); m=fmaxf(m,a0[46]);
    m=fmaxf(m,a0[88]); m=fmaxf(m,a0[89]); m=fmaxf(m,a0[90]);
    sm[OFF_ALIVE+idx]=(m>=0.1f)?1.0f:0.0f;
  }
  __syncthreads();

  /* masked = state * alive, channel-major 16 x 252 */
  for(int idx=tid; idx<1008; idx+=160){
    int p=idx>>2, c4=idx&3;
    int my=p/42, mx=p-my*42;
    int gy=y0-1+my, gx=mx-1;
    float4 v=make_float4(0.f,0.f,0.f,0.f);
    if((unsigned)gy<(unsigned)H_ && (unsigned)gx<(unsigned)W_)
      v=*(const float4*)&sb[(gy*W_+gx)*C_ + c4*4];
    float am=sm[OFF_ALIVE+p];
    int c0=c4*4;
    sm[OFF_MASK+(c0  )*252+p]=v.x*am;
    sm[OFF_MASK+(c0+1)*252+p]=v.y*am;
    sm[OFF_MASK+(c0+2)*252+p]=v.z*am;
    sm[OFF_MASK+(c0+3)*252+p]=v.w*am;
  }
  __syncthreads();

  /* per-lane perception: 48 values packed into 24 f32x2 */
  const int yl=tid/40, x=tid-yl*40;
  u64 pc[24];
  {
    float pf[48];
#pragma unroll
    for(int c=0;c<16;c++){
      const float* mB=&sm[OFF_MASK + c*252 + yl*42 + x];
      float m00=mB[0],  m01=mB[1],  m02=mB[2];
      float m10=mB[42], m11=mB[43], m12=mB[44];
      float m20=mB[84], m21=mB[85], m22=mB[86];
      pf[c]    = m11;
      pf[16+c] = ((m02+2.f*m12+m22)-(m00+2.f*m10+m20))*0.125f;
      pf[32+c] = ((m20+2.f*m21+m22)-(m00+2.f*m01+m02))*0.125f;
    }
#pragma unroll
    for(int k=0;k<24;k++) pc[k]=pkab(pf[2*k],pf[2*k+1]);
  }

  /* GEMM1+GEMM2 fused over hidden j (pairs); weights = uniform broadcasts */
  u64 out[8];
#pragma unroll
  for(int k=0;k<8;k++) out[k]=0ull;
  const ulonglong2* w1v=(const ulonglong2*)&sm[OFF_W1];
  const ulonglong2* w2v=(const ulonglong2*)&sm[OFF_W2];
#pragma unroll 2
  for(int j=0;j<128;j+=2){
    const ulonglong2* r0=w1v + j*12;
    const ulonglong2* r1=r0 + 12;
    u64 a0=0ull,b0=0ull,a1=0ull,b1v=0ull;
#pragma unroll
    for(int q=0;q<6;q++){
      ulonglong2 wa=r0[2*q], wb=r0[2*q+1];
      ulonglong2 wc=r1[2*q], wd=r1[2*q+1];
      a0 =ffma2(wa.x,pc[4*q+0],a0 ); b0 =ffma2(wa.y,pc[4*q+1],b0 );
      a1 =ffma2(wc.x,pc[4*q+0],a1 ); b1v=ffma2(wc.y,pc[4*q+1],b1v);
      a0 =ffma2(wb.x,pc[4*q+2],a0 ); b0 =ffma2(wb.y,pc[4*q+3],b0 );
      a1 =ffma2(wd.x,pc[4*q+2],a1 ); b1v=ffma2(wd.y,pc[4*q+3],b1v);
    }
    float l,h;
    upk(fadd2(a0,b0 ),l,h); float h0=fmaxf(l+h+sm[OFF_B1+j  ],0.f);
    upk(fadd2(a1,b1v),l,h); float h1=fmaxf(l+h+sm[OFF_B1+j+1],0.f);
    u64 hp0=pk2(h0), hp1=pk2(h1);
    const ulonglong2* c0=w2v + j*4;
#pragma unroll
    for(int q=0;q<4;q++){
      ulonglong2 w=c0[q];
      out[2*q  ]=ffma2(w.x,hp0,out[2*q  ]);
      out[2*q+1]=ffma2(w.y,hp0,out[2*q+1]);
    }
    const ulonglong2* c1=c0+4;
#pragma unroll
    for(int q=0;q<4;q++){
      ulonglong2 w=c1[q];
      out[2*q  ]=ffma2(w.x,hp1,out[2*q  ]);
      out[2*q+1]=ffma2(w.y,hp1,out[2*q+1]);
    }
  }

  /* residual + update-mask, write pre-state */
  {
    int gy=y0+yl, gx=x;
    float mf=(float)umask[(b*H_+gy)*W_+gx];
    float o_[16];
#pragma unroll
    for(int k=0;k<8;k++) upk(out[k], o_[2*k], o_[2*k+1]);
    const float4* s=(const float4*)&sb[(gy*W_+gx)*C_];
    float4* d=(float4*)(g_pre_buf+((size_t)(b*H_+gy)*W_+gx)*C_);
#pragma unroll
    for(int c4=0;c4<4;c4++){
      float4 a=s[c4];
      a.x+=mf*o_[4*c4+0]; a.y+=mf*o_[4*c4+1];
      a.z+=mf*o_[4*c4+2]; a.w+=mf*o_[4*c4+3];
      d[c4]=a;
    }
  }
}

/* ---- K2: new = pre * alive_mask(pre); store state + frame ---- */
__global__ void k_post(int nsel,int f,float* stkF,float* rgbF,unsigned char* rgbU){
  int pix=blockIdx.x*blockDim.x+threadIdx.x;
  if(pix>=NPIX_) return;
  int b=pix/(H_*W_); int rem=pix-b*(H_*W_); int y=rem/W_; int x=rem-y*W_;
  float m=-1e30f;
#pragma unroll
  for(int dy=-1;dy<=1;dy++){
    int yy=y+dy; if((unsigned)yy>=(unsigned)H_) continue;
#pragma unroll
    for(int dx=-1;dx<=1;dx++){
      int xx=x+dx; if((unsigned)xx>=(unsigned)W_) continue;
      m=fmaxf(m, g_pre_buf[((size_t)(b*H_+yy)*W_+xx)*C_+3]);
    }
  }
  float am=(m>=0.1f)?1.0f:0.0f;
  const float4* s=(const float4*)(g_pre_buf+(size_t)pix*C_);
  float4 v[4];
#pragma unroll
  for(int c4=0;c4<4;c4++){
    float4 t=s[c4];
    t.x*=am; t.y*=am; t.z*=am; t.w*=am;
    v[c4]=t;
  }
  float4* d=(float4*)(g_state_buf[nsel]+(size_t)pix*C_);
  d[0]=v[0];d[1]=v[1];d[2]=v[2];d[3]=v[3];
  write_frame(f,pix,v,stkF,rgbF,rgbU);
}

extern "C" void kernel_launch(void* const* d_in, const int* in_sizes, int n_in,
                              void* d_out, int out_size) {
  const float* st0=(const float*)d_in[0];
  const float* W1 =(const float*)d_in[1];
  const float* b1 =(const float*)d_in[2];
  const float* W2 =(const float*)d_in[3];
  const int*   um =(const int*)d_in[4];

  const long long SZ_RGB=33LL*NPIX_*3;     /* 20,275,200  */
  const long long SZ_STK=33LL*NPIX_*16;    /* 108,134,400 */

  float* stkF=0; float* rgbF=0; unsigned char* rgbU=0;
  long long osz=(long long)out_size;
  if(osz==SZ_RGB+SZ_STK){               /* float concat: rgb-as-float, then stacked */
    rgbF=(float*)d_out; stkF=(float*)d_out+SZ_RGB;
  }else if(osz==SZ_STK){                /* stacked only */
    stkF=(float*)d_out;
  }else if(osz==SZ_RGB){                /* rgb u8 only */
    rgbU=(unsigned char*)d_out;
  }else{                                /* byte concat: rgb u8, then stacked bytes */
    rgbU=(unsigned char*)d_out;
    stkF=(float*)((char*)d_out+SZ_RGB);
  }

  static int smem_set=0;
  if(!smem_set){
    cudaFuncSetAttribute(k_pre, cudaFuncAttributeMaxDynamicSharedMemorySize, SMEM_BYTES);
    smem_set=1;
  }

  const int TB=256, NB=(NPIX_+TB-1)/TB;
  k_init<<<NB,TB>>>(st0,stkF,rgbF,rgbU);
  int sel=0;
  for(int t=0;t<32;t++){
    k_pre<<<dim3(10,B_),160,SMEM_BYTES>>>(sel,W1,b1,W2,um+(size_t)t*NPIX_);
    k_post<<<NB,TB>>>(sel^1,t+1,stkF,rgbF,rgbU);
    sel^=1;
  }
}